// round 16
// baseline (speedup 1.0000x reference)
#include <cuda_runtime.h>
#include <cuda_bf16.h>
#include <cuda_fp16.h>
#include <cstdint>
#include <cstddef>

#define BB   4
#define CC   256
#define LL   4096
#define C8   32
#define OTOT 320   // 32 q + 32 k + 256 v rows

// ---------------- scratch (device globals; no allocation allowed) ----------
__device__ float g_bias[OTOT];
__device__ __align__(256) __half g_Wh[OTOT * CC];                     // packed [Wq;Wk;Wv] fp16
__device__ __align__(256) __half g_xh[(size_t)BB * LL * CC];          // x transposed fp16 [b][l][c]
__device__ __align__(256) __nv_bfloat16 g_vh[(size_t)BB * CC * LL];   // v in bf16
__device__ __align__(256) __half g_qT[(size_t)BB * LL * C8];          // q transposed fp16 [b][i][c]
__device__ __align__(256) __half g_kT[(size_t)BB * LL * C8];          // k transposed fp16 [b][j][c]

// ---------------- PTX helpers (sm_80-era only: family-target safe) ----------
__device__ __forceinline__ uint32_t smem_u32(const void* p) {
    uint32_t a;
    asm("{ .reg .u64 t; cvta.to.shared.u64 t, %1; cvt.u32.u64 %0, t; }" : "=r"(a) : "l"(p));
    return a;
}
__device__ __forceinline__ void cp_async16(uint32_t dst, const void* src) {
    asm volatile("cp.async.cg.shared.global [%0], [%1], 16;" :: "r"(dst), "l"(src));
}
#define CP_COMMIT() asm volatile("cp.async.commit_group;" ::: "memory")
#define CP_WAIT(n)  asm volatile("cp.async.wait_group %0;" :: "n"(n) : "memory")

__device__ __forceinline__ void ldsm4(uint32_t* r, uint32_t addr) {
    asm volatile("ldmatrix.sync.aligned.m8n8.x4.shared.b16 {%0,%1,%2,%3}, [%4];"
                 : "=r"(r[0]), "=r"(r[1]), "=r"(r[2]), "=r"(r[3]) : "r"(addr));
}
__device__ __forceinline__ void mma16816_bf16(float* d, const uint32_t* a, const uint32_t* b) {
    asm volatile(
        "mma.sync.aligned.m16n8k16.row.col.f32.bf16.bf16.f32 "
        "{%0,%1,%2,%3}, {%4,%5,%6,%7}, {%8,%9}, {%0,%1,%2,%3};"
        : "+f"(d[0]), "+f"(d[1]), "+f"(d[2]), "+f"(d[3])
        : "r"(a[0]), "r"(a[1]), "r"(a[2]), "r"(a[3]), "r"(b[0]), "r"(b[1]));
}
__device__ __forceinline__ void mma16816_f16(float* d, const uint32_t* a, const uint32_t* b) {
    asm volatile(
        "mma.sync.aligned.m16n8k16.row.col.f32.f16.f16.f32 "
        "{%0,%1,%2,%3}, {%4,%5,%6,%7}, {%8,%9}, {%0,%1,%2,%3};"
        : "+f"(d[0]), "+f"(d[1]), "+f"(d[2]), "+f"(d[3])
        : "r"(a[0]), "r"(a[1]), "r"(a[2]), "r"(a[3]), "r"(b[0]), "r"(b[1]));
}

// SW64 swizzle for 64-byte rows.
__device__ __forceinline__ uint32_t sw64(uint32_t off) {
    return off ^ ((off >> 3) & 0x30);
}

// ---------------- kernel 0: pack weights (fp16) + biases --------------------
__global__ void pack_kernel(const float* __restrict__ Wq, const float* __restrict__ bq,
                            const float* __restrict__ Wk, const float* __restrict__ bk,
                            const float* __restrict__ Wv, const float* __restrict__ bv) {
    int tid = blockIdx.x * blockDim.x + threadIdx.x;
    int stride = gridDim.x * blockDim.x;
    for (int idx = tid; idx < OTOT * CC; idx += stride) {
        int o = idx / CC;
        int c = idx % CC;
        float w;
        if (o < 32)       w = Wq[o * CC + c];
        else if (o < 64)  w = Wk[(o - 32) * CC + c];
        else              w = Wv[(o - 64) * CC + c];
        g_Wh[idx] = __float2half(w);
    }
    if (tid < OTOT) {
        g_bias[tid] = (tid < 32) ? bq[tid] : (tid < 64) ? bk[tid - 32] : bv[tid - 64];
    }
}

// ---------------- kernel 0b: xT = transpose(x) in fp16 ----------------------
__global__ __launch_bounds__(256) void xt_kernel(const float* __restrict__ x) {
    __shared__ float s[64][65];
    const int b  = blockIdx.z;
    const int c0 = blockIdx.y * 64;
    const int l0 = blockIdx.x * 64;
    const int t  = threadIdx.x;

    for (int i = t; i < 64 * 64; i += 256) {
        int r  = i >> 6;
        int cl = i & 63;
        s[r][cl] = x[((size_t)b * CC + c0 + r) * LL + l0 + cl];
    }
    __syncthreads();
    for (int i = t; i < 64 * 32; i += 256) {
        int r2 = i >> 5;
        int c2 = (i & 31) * 2;
        __half2 h = __floats2half2_rn(s[c2][r2], s[c2 + 1][r2]);
        *(__half2*)&g_xh[((size_t)b * LL + l0 + r2) * CC + c0 + c2] = h;
    }
}

// ---------------- kernel 1: qkvT[o][l] = W[o][c] . xT[l][c] via mma ---------
__global__ __launch_bounds__(256) void qkvT_kernel() {
    __shared__ __align__(1024) uint8_t sW[2][4096];
    __shared__ __align__(1024) uint8_t sX[2][16384];
    __shared__ float sBias[64];

    const int b  = blockIdx.z;
    const int oy = blockIdx.y;          // 0..4
    const int o0 = oy * 64;
    const int l0 = blockIdx.x * 256;

    const int t  = threadIdx.x;
    const int w  = t >> 5;
    const int l  = t & 31;
    const int wn = w;

    const uint32_t sWa = smem_u32(sW);
    const uint32_t sXa = smem_u32(sX);

    const int ra = t >> 2;
    const int ca = t & 3;
    const __half* Wg = g_Wh + (o0 + ra) * CC + ca * 8;
    const __half* Xg = g_xh + ((size_t)b * LL + l0 + ra) * CC + ca * 8;
    const uint32_t aoff = sw64((uint32_t)ra * 64u + (uint32_t)ca * 16u);
    uint32_t xoff[4];
#pragma unroll
    for (int r = 0; r < 4; r++)
        xoff[r] = sw64((uint32_t)(ra + 64 * r) * 64u + (uint32_t)ca * 16u);

    if (t < 64) sBias[t] = g_bias[o0 + t];

    cp_async16(sWa + aoff, Wg);
#pragma unroll
    for (int r = 0; r < 4; r++)
        cp_async16(sXa + xoff[r], Xg + (size_t)(64 * r) * CC);
    CP_COMMIT();

    float acc[4][4][4];
#pragma unroll
    for (int i = 0; i < 4; i++)
#pragma unroll
        for (int j = 0; j < 4; j++)
#pragma unroll
            for (int v = 0; v < 4; v++) acc[i][j][v] = 0.f;

    const int arow = (l & 15);
    const int ac16 = l >> 4;
    const int brow = wn * 32 + (l & 7) + ((l >> 4) << 3);
    const int bc16 = (l >> 3) & 1;

    const int NKQ = CC / 32;   // 8
    for (int kt = 0; kt < NKQ; kt++) {
        const int buf = kt & 1;
        if (kt + 1 < NKQ) {
            const uint32_t dw = sWa + (buf ^ 1) * 4096;
            const uint32_t dx = sXa + (buf ^ 1) * 16384;
            cp_async16(dw + aoff, Wg + (kt + 1) * 32);
#pragma unroll
            for (int r = 0; r < 4; r++)
                cp_async16(dx + xoff[r], Xg + (size_t)(64 * r) * CC + (kt + 1) * 32);
            CP_COMMIT();
            CP_WAIT(1);
        } else {
            CP_WAIT(0);
        }
        __syncthreads();

        const uint32_t ab = sWa + buf * 4096;
        const uint32_t bb = sXa + buf * 16384;
#pragma unroll
        for (int ks = 0; ks < 2; ks++) {
            uint32_t afr[4][4];
#pragma unroll
            for (int im = 0; im < 4; im++) {
                int row = arow + im * 16;
                int c16 = ks * 2 + ac16;
                uint32_t off = (uint32_t)row * 64u + (uint32_t)((c16 ^ ((row & 6) >> 1)) * 16);
                ldsm4(afr[im], ab + off);
            }
            uint32_t bfr[2][4];
#pragma unroll
            for (int ig = 0; ig < 2; ig++) {
                int row = brow + ig * 16;
                int c16 = ks * 2 + bc16;
                uint32_t off = (uint32_t)row * 64u + (uint32_t)((c16 ^ ((row & 6) >> 1)) * 16);
                ldsm4(bfr[ig], bb + off);
            }
#pragma unroll
            for (int im = 0; im < 4; im++)
#pragma unroll
                for (int ig = 0; ig < 2; ig++) {
                    mma16816_f16(acc[im][ig * 2 + 0], afr[im], &bfr[ig][0]);
                    mma16816_f16(acc[im][ig * 2 + 1], afr[im], &bfr[ig][2]);
                }
        }
        __syncthreads();
    }

    const int lr  = l >> 2;
    const int lc2 = 2 * (l & 3);

#pragma unroll
    for (int im = 0; im < 4; im++) {
        const int or0 = im * 16 + lr;
        const int or1 = or0 + 8;
        const float b0 = sBias[or0];
        const float b1 = sBias[or1];
#pragma unroll
        for (int jn = 0; jn < 4; jn++) {
            const int lc = wn * 32 + jn * 8 + lc2;
            float v00 = acc[im][jn][0] + b0, v01 = acc[im][jn][1] + b0;
            float v10 = acc[im][jn][2] + b1, v11 = acc[im][jn][3] + b1;

            if (oy == 0) {
                const size_t lidx = (size_t)b * LL + l0 + lc;
                if (im < 2) {
                    g_qT[lidx * C8 + or0]       = __float2half(v00);
                    g_qT[(lidx + 1) * C8 + or0] = __float2half(v01);
                    g_qT[lidx * C8 + or1]       = __float2half(v10);
                    g_qT[(lidx + 1) * C8 + or1] = __float2half(v11);
                } else {
                    g_kT[lidx * C8 + or0 - 32]       = __float2half(v00);
                    g_kT[(lidx + 1) * C8 + or0 - 32] = __float2half(v01);
                    g_kT[lidx * C8 + or1 - 32]       = __float2half(v10);
                    g_kT[(lidx + 1) * C8 + or1 - 32] = __float2half(v11);
                }
            } else {
                const int vr0 = (oy - 1) * 64 + or0;
                const int vr1 = vr0 + 8;
                *(__nv_bfloat162*)&g_vh[((size_t)b * CC + vr0) * LL + l0 + lc] =
                    __floats2bfloat162_rn(v00, v01);
                *(__nv_bfloat162*)&g_vh[((size_t)b * CC + vr1) * LL + l0 + lc] =
                    __floats2bfloat162_rn(v10, v11);
            }
        }
    }
}

// ---------------- kernel 2 (FUSED, pipelined): ------------------------------
// out = gamma*(V @ softmax(qK)^T) + x. One CTA per (b, 128-query i-tile),
// 512 threads = 16 warps. ONE barrier per j-tile; P double-buffered so
// QK(jt+1)+exp overlaps (across warps) with PV(jt).
//   iter jt: [wait cp][barrier] -> prefetch V(jt+1),K(jt+2)
//            -> QK(jt+1) -> exp -> P[(jt+1)%2]   (no barrier)
//            -> PV(jt) from P[jt%2], V[jt%2]
#define NJT 32
// smem layout (bytes, dynamic):
#define FOFF_Q   0          //   8 KB : Q tile 128 x 64B
#define FOFF_K   8192       //  16 KB : K tiles 2 x (128 x 64B)
#define FOFF_P   24576      //  64 KB : P tiles 2 x 4 segs x (128 x 64B)
#define FOFF_V   90112      // 128 KB : V tiles 2 x 4 segs x (256 x 64B)
#define FOFF_SRS 221184     //   2 KB : rowsum staging [4][128]
#define FOFF_INV 223232     // 512 B  : 1/rowsum [128]
#define FSM_TOTAL 223744

__global__ __launch_bounds__(512, 1) void fused_attn_kernel(
        const float* __restrict__ x, const float* __restrict__ gamma,
        float* __restrict__ out) {
    extern __shared__ __align__(1024) uint8_t smf[];
    const uint32_t sb  = smem_u32(smf);
    const uint32_t sQa = sb + FOFF_Q;
    const uint32_t sKa = sb + FOFF_K;
    const uint32_t sPa = sb + FOFF_P;
    const uint32_t sVa = sb + FOFF_V;
    float* srs  = (float*)(smf + FOFF_SRS);
    float* sInv = (float*)(smf + FOFF_INV);

    const int b  = blockIdx.y;
    const int i0 = blockIdx.x * 128;

    const int t = threadIdx.x;
    const int w = t >> 5;
    const int l = t & 31;
    // QK warp layout: 4(m: 32 i-rows) x 4(n: 32 j-cols)
    const int wm = w & 3;
    const int wn = w >> 2;
    // PV warp layout: 4(c: 64 rows) x 4(i: 32 cols)
    const int cm = w & 3;
    const int in_ = w >> 2;

    // Q/K loader: one 16B chunk per thread (128 rows x 4 chunks)
    const int ldr = t >> 2;
    const int ldc = t & 3;
    const uint32_t loff = sw64((uint32_t)ldr * 64u + (uint32_t)ldc * 16u);
    // V loader: row = t/2, half = t&1 (128B contiguous per thread)
    const int vrow = t >> 1;
    const int vh   = t & 1;

    // fragment index precomputation
    const int qarow = wm * 32 + (l & 15);
    const int qac16 = l >> 4;
    const int kbrow = wn * 32 + (l & 7) + ((l >> 4) << 3);
    const int kbc16 = (l >> 3) & 1;
    const int varow = cm * 64 + (l & 15);
    const int vac16 = l >> 4;
    const int pbrow = in_ * 32 + (l & 7) + ((l >> 4) << 3);
    const int pbc16 = (l >> 3) & 1;
    const int rl0   = wm * 32 + (l >> 2);

    float accD[4][4][4];
#pragma unroll
    for (int i = 0; i < 4; i++)
#pragma unroll
        for (int j = 0; j < 4; j++)
#pragma unroll
            for (int v = 0; v < 4; v++) accD[i][j][v] = 0.f;
    float rsum[4] = {0.f, 0.f, 0.f, 0.f};

    // preload Q fragments after prologue (below); Q stays in smem.

    // ---- QK(s) + exp -> P[s&1] (per-warp, no barrier) ----
    auto qk_exp = [&](int s) {
        const uint32_t kb = sKa + (s & 1) * 8192u;
        const uint32_t pB = (uint32_t)FOFF_P + (s & 1) * 32768u + (uint32_t)wn * 8192u;

        float S[2][4][4];
#pragma unroll
        for (int i = 0; i < 2; i++)
#pragma unroll
            for (int j = 0; j < 4; j++)
#pragma unroll
                for (int v = 0; v < 4; v++) S[i][j][v] = 0.f;

#pragma unroll
        for (int ks = 0; ks < 2; ks++) {
            uint32_t aq[2][4];
#pragma unroll
            for (int im = 0; im < 2; im++) {
                int row = qarow + im * 16;
                int c16 = ks * 2 + qac16;
                ldsm4(aq[im], sQa + (uint32_t)row * 64u +
                                  (uint32_t)((c16 ^ ((row & 6) >> 1)) * 16));
            }
            uint32_t bk_[2][4];
#pragma unroll
            for (int ig = 0; ig < 2; ig++) {
                int row = kbrow + ig * 16;
                int c16 = ks * 2 + kbc16;
                ldsm4(bk_[ig], kb + (uint32_t)row * 64u +
                                   (uint32_t)((c16 ^ ((row & 6) >> 1)) * 16));
            }
#pragma unroll
            for (int im = 0; im < 2; im++)
#pragma unroll
                for (int ig = 0; ig < 2; ig++) {
                    mma16816_f16(S[im][ig * 2 + 0], aq[im], &bk_[ig][0]);
                    mma16816_f16(S[im][ig * 2 + 1], aq[im], &bk_[ig][2]);
                }
        }

#pragma unroll
        for (int im = 0; im < 2; im++) {
            const int row0 = rl0 + im * 16;
            const int row1 = row0 + 8;
            float s0 = 0.f, s1 = 0.f;
#pragma unroll
            for (int jn = 0; jn < 4; jn++) {
                float e0 = __expf(S[im][jn][0]);
                float e1 = __expf(S[im][jn][1]);
                float e2 = __expf(S[im][jn][2]);
                float e3 = __expf(S[im][jn][3]);
                uint32_t o0 = pB + sw64((uint32_t)row0 * 64u + (uint32_t)jn * 16u) + 4 * (l & 3);
                uint32_t o1 = pB + sw64((uint32_t)row1 * 64u + (uint32_t)jn * 16u) + 4 * (l & 3);
                *(__nv_bfloat162*)(smf + o0) = __floats2bfloat162_rn(e0, e1);
                *(__nv_bfloat162*)(smf + o1) = __floats2bfloat162_rn(e2, e3);
                s0 += e0 + e1;
                s1 += e2 + e3;
            }
            rsum[im * 2 + 0] += s0;
            rsum[im * 2 + 1] += s1;
        }
    };

    // ---- prologue: Q + K0 + K1 + V0 in one group ----
    {
        const __half* Qg = g_qT + ((size_t)b * LL + i0 + ldr) * C8 + ldc * 8;
        cp_async16(sQa + loff, Qg);
        const __half* Kg0 = g_kT + ((size_t)b * LL + ldr) * C8 + ldc * 8;
        cp_async16(sKa + loff, Kg0);
        const __half* Kg1 = g_kT + ((size_t)b * LL + 128 + ldr) * C8 + ldc * 8;
        cp_async16(sKa + 8192 + loff, Kg1);
        const __nv_bfloat16* Vg = g_vh + ((size_t)b * CC + vrow) * LL + vh * 64;
#pragma unroll
        for (int q = 0; q < 8; q++) {
            int sc = vh * 2 + (q >> 2);
            cp_async16(sVa + sc * 16384 + sw64((uint32_t)vrow * 64u + (uint32_t)(q & 3) * 16u),
                       Vg + q * 8);
        }
        CP_COMMIT();
        CP_WAIT(0);
        __syncthreads();
    }

    // QK(0) -> P[0]
    qk_exp(0);

    for (int jt = 0; jt < NJT; jt++) {
        // V(jt), K(jt+1) resident (committed at jt-1; full iteration of slack)
        CP_WAIT(0);
        __syncthreads();   // P(jt) sealed by all warps; stale buffers free

        // prefetch V(jt+1) -> vbuf[(jt+1)&1], K(jt+2) -> kbuf[jt&1]
        if (jt + 1 < NJT) {
            const __nv_bfloat16* Vg =
                g_vh + ((size_t)b * CC + vrow) * LL + (size_t)(jt + 1) * 128 + vh * 64;
            const uint32_t dst = sVa + ((jt + 1) & 1) * 65536;
#pragma unroll
            for (int q = 0; q < 8; q++) {
                int sc = vh * 2 + (q >> 2);
                cp_async16(dst + sc * 16384 +
                               sw64((uint32_t)vrow * 64u + (uint32_t)(q & 3) * 16u),
                           Vg + q * 8);
            }
            if (jt + 2 < NJT) {
                const __half* Kg2 =
                    g_kT + ((size_t)b * LL + (size_t)(jt + 2) * 128 + ldr) * C8 + ldc * 8;
                cp_async16(sKa + (jt & 1) * 8192 + loff, Kg2);
            }
            CP_COMMIT();
        }

        // QK(jt+1) + exp -> P[(jt+1)&1]  (K(jt+1) resident; no barrier needed)
        if (jt + 1 < NJT) qk_exp(jt + 1);

        // ---- PV(jt): accD += V[64c x 32j] * P[32i x 32j]^T, 4 sub-chunks ----
        const uint32_t vb = sVa + (jt & 1) * 65536;
        const uint32_t pT = sPa + (jt & 1) * 32768;
#pragma unroll
        for (int sc = 0; sc < 4; sc++) {
            const uint32_t va = vb + sc * 16384;
            const uint32_t pa = pT + sc * 8192;
#pragma unroll
            for (int ks = 0; ks < 2; ks++) {
                uint32_t af[4][4];
#pragma unroll
                for (int imm = 0; imm < 4; imm++) {
                    int row = varow + imm * 16;
                    int c16 = ks * 2 + vac16;
                    ldsm4(af[imm], va + (uint32_t)row * 64u +
                                       (uint32_t)((c16 ^ ((row & 6) >> 1)) * 16));
                }
                uint32_t bp[2][4];
#pragma unroll
                for (int ig = 0; ig < 2; ig++) {
                    int row = pbrow + ig * 16;
                    int c16 = ks * 2 + pbc16;
                    ldsm4(bp[ig], pa + (uint32_t)row * 64u +
                                      (uint32_t)((c16 ^ ((row & 6) >> 1)) * 16));
                }
#pragma unroll
                for (int imm = 0; imm < 4; imm++)
#pragma unroll
                    for (int ig = 0; ig < 2; ig++) {
                        mma16816_bf16(accD[imm][ig * 2 + 0], af[imm], &bp[ig][0]);
                        mma16816_bf16(accD[imm][ig * 2 + 1], af[imm], &bp[ig][2]);
                    }
            }
        }
    }

    // ---- rowsum: quad shfl, stage per-wn, reduce ----
#pragma unroll
    for (int off = 1; off <= 2; off <<= 1)
#pragma unroll
        for (int r = 0; r < 4; r++)
            rsum[r] += __shfl_xor_sync(0xffffffffu, rsum[r], off);

    if ((l & 3) == 0) {
        srs[wn * 128 + rl0]      = rsum[0];
        srs[wn * 128 + rl0 + 8]  = rsum[1];
        srs[wn * 128 + rl0 + 16] = rsum[2];
        srs[wn * 128 + rl0 + 24] = rsum[3];
    }
    __syncthreads();
    if (t < 128)
        sInv[t] = 1.0f / (srs[t] + srs[128 + t] + srs[256 + t] + srs[384 + t]);
    __syncthreads();

    // ---- epilogue: normalize, gamma, residual ----
    const float g = *gamma;
#pragma unroll
    for (int imm = 0; imm < 4; imm++) {
        const int r0 = cm * 64 + imm * 16 + (l >> 2);
#pragma unroll
        for (int jn = 0; jn < 4; jn++) {
            const int ic = in_ * 32 + jn * 8 + 2 * (l & 3);
            float2 inv = *(float2*)&sInv[ic];

            size_t base0 = ((size_t)b * CC + r0) * LL + i0 + ic;
            float2 xv0 = *(const float2*)&x[base0];
            float2 o0;
            o0.x = g * accD[imm][jn][0] * inv.x + xv0.x;
            o0.y = g * accD[imm][jn][1] * inv.y + xv0.y;
            *(float2*)&out[base0] = o0;

            size_t base1 = base0 + (size_t)8 * LL;
            float2 xv1 = *(const float2*)&x[base1];
            float2 o1;
            o1.x = g * accD[imm][jn][2] * inv.x + xv1.x;
            o1.y = g * accD[imm][jn][3] * inv.y + xv1.y;
            *(float2*)&out[base1] = o1;
        }
    }
}

// ---------------- launch ----------------------------------------------------
extern "C" void kernel_launch(void* const* d_in, const int* in_sizes, int n_in,
                              void* d_out, int out_size) {
    const float* x     = (const float*)d_in[0];
    const float* Wq    = (const float*)d_in[1];
    const float* bq    = (const float*)d_in[2];
    const float* Wk    = (const float*)d_in[3];
    const float* bk    = (const float*)d_in[4];
    const float* Wv    = (const float*)d_in[5];
    const float* bv    = (const float*)d_in[6];
    const float* gamma = (const float*)d_in[7];
    float* out = (float*)d_out;

    cudaFuncSetAttribute(fused_attn_kernel,
                         cudaFuncAttributeMaxDynamicSharedMemorySize, FSM_TOTAL);

    pack_kernel<<<320, 256>>>(Wq, bq, Wk, bk, Wv, bv);
    xt_kernel<<<dim3(LL / 64, CC / 64, BB), 256>>>(x);
    qkvT_kernel<<<dim3(LL / 256, OTOT / 64, BB), 256>>>();
    fused_attn_kernel<<<dim3(LL / 128, BB), 512, FSM_TOTAL>>>(x, gamma, out);
}

// round 17
// speedup vs baseline: 1.0504x; 1.0504x over previous
#include <cuda_runtime.h>
#include <cuda_bf16.h>
#include <cuda_fp16.h>
#include <cstdint>
#include <cstddef>

#define BB   4
#define CC   256
#define LL   4096
#define C8   32
#define OTOT 320   // 32 q + 32 k + 256 v rows

// ---------------- scratch (device globals; no allocation allowed) ----------
__device__ float g_bias[OTOT];
__device__ __align__(256) __half g_Wh[OTOT * CC];                     // packed [Wq;Wk;Wv] fp16
__device__ __align__(256) __half g_xh[(size_t)BB * LL * CC];          // x transposed fp16 [b][l][c]
__device__ __align__(256) __nv_bfloat16 g_vh[(size_t)BB * CC * LL];   // v in bf16
__device__ __align__(256) __half g_qT[(size_t)BB * LL * C8];          // q transposed fp16 [b][i][c]
__device__ __align__(256) __half g_kT[(size_t)BB * LL * C8];          // k transposed fp16 [b][j][c]

// ---------------- PTX helpers (sm_80-era only: family-target safe) ----------
__device__ __forceinline__ uint32_t smem_u32(const void* p) {
    uint32_t a;
    asm("{ .reg .u64 t; cvta.to.shared.u64 t, %1; cvt.u32.u64 %0, t; }" : "=r"(a) : "l"(p));
    return a;
}
__device__ __forceinline__ void cp_async16(uint32_t dst, const void* src) {
    asm volatile("cp.async.cg.shared.global [%0], [%1], 16;" :: "r"(dst), "l"(src));
}
#define CP_COMMIT() asm volatile("cp.async.commit_group;" ::: "memory")
#define CP_WAIT(n)  asm volatile("cp.async.wait_group %0;" :: "n"(n) : "memory")

__device__ __forceinline__ void ldsm4(uint32_t* r, uint32_t addr) {
    asm volatile("ldmatrix.sync.aligned.m8n8.x4.shared.b16 {%0,%1,%2,%3}, [%4];"
                 : "=r"(r[0]), "=r"(r[1]), "=r"(r[2]), "=r"(r[3]) : "r"(addr));
}
__device__ __forceinline__ void mma16816_bf16(float* d, const uint32_t* a, const uint32_t* b) {
    asm volatile(
        "mma.sync.aligned.m16n8k16.row.col.f32.bf16.bf16.f32 "
        "{%0,%1,%2,%3}, {%4,%5,%6,%7}, {%8,%9}, {%0,%1,%2,%3};"
        : "+f"(d[0]), "+f"(d[1]), "+f"(d[2]), "+f"(d[3])
        : "r"(a[0]), "r"(a[1]), "r"(a[2]), "r"(a[3]), "r"(b[0]), "r"(b[1]));
}
__device__ __forceinline__ void mma16816_f16(float* d, const uint32_t* a, const uint32_t* b) {
    asm volatile(
        "mma.sync.aligned.m16n8k16.row.col.f32.f16.f16.f32 "
        "{%0,%1,%2,%3}, {%4,%5,%6,%7}, {%8,%9}, {%0,%1,%2,%3};"
        : "+f"(d[0]), "+f"(d[1]), "+f"(d[2]), "+f"(d[3])
        : "r"(a[0]), "r"(a[1]), "r"(a[2]), "r"(a[3]), "r"(b[0]), "r"(b[1]));
}

// SW64 swizzle for 64-byte rows.
__device__ __forceinline__ uint32_t sw64(uint32_t off) {
    return off ^ ((off >> 3) & 0x30);
}

// ---------------- kernel 0: pack weights (fp16) + biases --------------------
__global__ void pack_kernel(const float* __restrict__ Wq, const float* __restrict__ bq,
                            const float* __restrict__ Wk, const float* __restrict__ bk,
                            const float* __restrict__ Wv, const float* __restrict__ bv) {
    int tid = blockIdx.x * blockDim.x + threadIdx.x;
    int stride = gridDim.x * blockDim.x;
    for (int idx = tid; idx < OTOT * CC; idx += stride) {
        int o = idx / CC;
        int c = idx % CC;
        float w;
        if (o < 32)       w = Wq[o * CC + c];
        else if (o < 64)  w = Wk[(o - 32) * CC + c];
        else              w = Wv[(o - 64) * CC + c];
        g_Wh[idx] = __float2half(w);
    }
    if (tid < OTOT) {
        g_bias[tid] = (tid < 32) ? bq[tid] : (tid < 64) ? bk[tid - 32] : bv[tid - 64];
    }
}

// ---------------- kernel 0b: xT = transpose(x) in fp16 ----------------------
__global__ __launch_bounds__(256) void xt_kernel(const float* __restrict__ x) {
    __shared__ float s[64][65];
    const int b  = blockIdx.z;
    const int c0 = blockIdx.y * 64;
    const int l0 = blockIdx.x * 64;
    const int t  = threadIdx.x;

    for (int i = t; i < 64 * 64; i += 256) {
        int r  = i >> 6;
        int cl = i & 63;
        s[r][cl] = x[((size_t)b * CC + c0 + r) * LL + l0 + cl];
    }
    __syncthreads();
    for (int i = t; i < 64 * 32; i += 256) {
        int r2 = i >> 5;
        int c2 = (i & 31) * 2;
        __half2 h = __floats2half2_rn(s[c2][r2], s[c2 + 1][r2]);
        *(__half2*)&g_xh[((size_t)b * LL + l0 + r2) * CC + c0 + c2] = h;
    }
}

// ---------------- kernel 1: qkvT[o][l] = W[o][c] . xT[l][c] via mma ---------
__global__ __launch_bounds__(256) void qkvT_kernel() {
    __shared__ __align__(1024) uint8_t sW[2][4096];
    __shared__ __align__(1024) uint8_t sX[2][16384];
    __shared__ float sBias[64];

    const int b  = blockIdx.z;
    const int oy = blockIdx.y;          // 0..4
    const int o0 = oy * 64;
    const int l0 = blockIdx.x * 256;

    const int t  = threadIdx.x;
    const int w  = t >> 5;
    const int l  = t & 31;
    const int wn = w;

    const uint32_t sWa = smem_u32(sW);
    const uint32_t sXa = smem_u32(sX);

    const int ra = t >> 2;
    const int ca = t & 3;
    const __half* Wg = g_Wh + (o0 + ra) * CC + ca * 8;
    const __half* Xg = g_xh + ((size_t)b * LL + l0 + ra) * CC + ca * 8;
    const uint32_t aoff = sw64((uint32_t)ra * 64u + (uint32_t)ca * 16u);
    uint32_t xoff[4];
#pragma unroll
    for (int r = 0; r < 4; r++)
        xoff[r] = sw64((uint32_t)(ra + 64 * r) * 64u + (uint32_t)ca * 16u);

    if (t < 64) sBias[t] = g_bias[o0 + t];

    cp_async16(sWa + aoff, Wg);
#pragma unroll
    for (int r = 0; r < 4; r++)
        cp_async16(sXa + xoff[r], Xg + (size_t)(64 * r) * CC);
    CP_COMMIT();

    float acc[4][4][4];
#pragma unroll
    for (int i = 0; i < 4; i++)
#pragma unroll
        for (int j = 0; j < 4; j++)
#pragma unroll
            for (int v = 0; v < 4; v++) acc[i][j][v] = 0.f;

    const int arow = (l & 15);
    const int ac16 = l >> 4;
    const int brow = wn * 32 + (l & 7) + ((l >> 4) << 3);
    const int bc16 = (l >> 3) & 1;

    const int NKQ = CC / 32;   // 8
    for (int kt = 0; kt < NKQ; kt++) {
        const int buf = kt & 1;
        if (kt + 1 < NKQ) {
            const uint32_t dw = sWa + (buf ^ 1) * 4096;
            const uint32_t dx = sXa + (buf ^ 1) * 16384;
            cp_async16(dw + aoff, Wg + (kt + 1) * 32);
#pragma unroll
            for (int r = 0; r < 4; r++)
                cp_async16(dx + xoff[r], Xg + (size_t)(64 * r) * CC + (kt + 1) * 32);
            CP_COMMIT();
            CP_WAIT(1);
        } else {
            CP_WAIT(0);
        }
        __syncthreads();

        const uint32_t ab = sWa + buf * 4096;
        const uint32_t bb = sXa + buf * 16384;
#pragma unroll
        for (int ks = 0; ks < 2; ks++) {
            uint32_t afr[4][4];
#pragma unroll
            for (int im = 0; im < 4; im++) {
                int row = arow + im * 16;
                int c16 = ks * 2 + ac16;
                uint32_t off = (uint32_t)row * 64u + (uint32_t)((c16 ^ ((row & 6) >> 1)) * 16);
                ldsm4(afr[im], ab + off);
            }
            uint32_t bfr[2][4];
#pragma unroll
            for (int ig = 0; ig < 2; ig++) {
                int row = brow + ig * 16;
                int c16 = ks * 2 + bc16;
                uint32_t off = (uint32_t)row * 64u + (uint32_t)((c16 ^ ((row & 6) >> 1)) * 16);
                ldsm4(bfr[ig], bb + off);
            }
#pragma unroll
            for (int im = 0; im < 4; im++)
#pragma unroll
                for (int ig = 0; ig < 2; ig++) {
                    mma16816_f16(acc[im][ig * 2 + 0], afr[im], &bfr[ig][0]);
                    mma16816_f16(acc[im][ig * 2 + 1], afr[im], &bfr[ig][2]);
                }
        }
        __syncthreads();
    }

    const int lr  = l >> 2;
    const int lc2 = 2 * (l & 3);

#pragma unroll
    for (int im = 0; im < 4; im++) {
        const int or0 = im * 16 + lr;
        const int or1 = or0 + 8;
        const float b0 = sBias[or0];
        const float b1 = sBias[or1];
#pragma unroll
        for (int jn = 0; jn < 4; jn++) {
            const int lc = wn * 32 + jn * 8 + lc2;
            float v00 = acc[im][jn][0] + b0, v01 = acc[im][jn][1] + b0;
            float v10 = acc[im][jn][2] + b1, v11 = acc[im][jn][3] + b1;

            if (oy == 0) {
                const size_t lidx = (size_t)b * LL + l0 + lc;
                if (im < 2) {
                    g_qT[lidx * C8 + or0]       = __float2half(v00);
                    g_qT[(lidx + 1) * C8 + or0] = __float2half(v01);
                    g_qT[lidx * C8 + or1]       = __float2half(v10);
                    g_qT[(lidx + 1) * C8 + or1] = __float2half(v11);
                } else {
                    g_kT[lidx * C8 + or0 - 32]       = __float2half(v00);
                    g_kT[(lidx + 1) * C8 + or0 - 32] = __float2half(v01);
                    g_kT[lidx * C8 + or1 - 32]       = __float2half(v10);
                    g_kT[(lidx + 1) * C8 + or1 - 32] = __float2half(v11);
                }
            } else {
                const int vr0 = (oy - 1) * 64 + or0;
                const int vr1 = vr0 + 8;
                *(__nv_bfloat162*)&g_vh[((size_t)b * CC + vr0) * LL + l0 + lc] =
                    __floats2bfloat162_rn(v00, v01);
                *(__nv_bfloat162*)&g_vh[((size_t)b * CC + vr1) * LL + l0 + lc] =
                    __floats2bfloat162_rn(v10, v11);
            }
        }
    }
}

// ---------------- kernel 2 (FUSED, register-pressure-reduced): --------------
// out = gamma*(V @ softmax(qK)^T) + x. One CTA per (b, 128-query i-tile),
// 512 threads = 16 warps. One barrier per j-tile; P double-buffered.
// QK computed in two im-halves (S live range 16 regs, not 32); PV A-fragments
// loaded in imm-pairs (8 regs, not 16) -> peak regs < 128 cap, no spills.
#define NJT 32
// smem layout (bytes, dynamic):
#define FOFF_Q   0          //   8 KB : Q tile 128 x 64B
#define FOFF_K   8192       //  16 KB : K tiles 2 x (128 x 64B)
#define FOFF_P   24576      //  64 KB : P tiles 2 x 4 segs x (128 x 64B)
#define FOFF_V   90112      // 128 KB : V tiles 2 x 4 segs x (256 x 64B)
#define FOFF_SRS 221184     //   2 KB : rowsum staging [4][128]
#define FOFF_INV 223232     // 512 B  : 1/rowsum [128]
#define FSM_TOTAL 223744

__global__ __launch_bounds__(512, 1) void fused_attn_kernel(
        const float* __restrict__ x, const float* __restrict__ gamma,
        float* __restrict__ out) {
    extern __shared__ __align__(1024) uint8_t smf[];
    const uint32_t sb  = smem_u32(smf);
    const uint32_t sQa = sb + FOFF_Q;
    const uint32_t sKa = sb + FOFF_K;
    const uint32_t sPa = sb + FOFF_P;
    const uint32_t sVa = sb + FOFF_V;
    float* srs  = (float*)(smf + FOFF_SRS);
    float* sInv = (float*)(smf + FOFF_INV);

    const int b  = blockIdx.y;
    const int i0 = blockIdx.x * 128;

    const int t = threadIdx.x;
    const int w = t >> 5;
    const int l = t & 31;
    // QK warp layout: 4(m: 32 i-rows) x 4(n: 32 j-cols)
    const int wm = w & 3;
    const int wn = w >> 2;
    // PV warp layout: 4(c: 64 rows) x 4(i: 32 cols)
    const int cm = w & 3;
    const int in_ = w >> 2;

    // Q/K loader: one 16B chunk per thread (128 rows x 4 chunks)
    const int ldr = t >> 2;
    const int ldc = t & 3;
    const uint32_t loff = sw64((uint32_t)ldr * 64u + (uint32_t)ldc * 16u);
    // V loader: row = t/2, half = t&1 (128B contiguous per thread)
    const int vrow = t >> 1;
    const int vh   = t & 1;

    // fragment index precomputation
    const int qarow = wm * 32 + (l & 15);
    const int qac16 = l >> 4;
    const int kbrow = wn * 32 + (l & 7) + ((l >> 4) << 3);
    const int kbc16 = (l >> 3) & 1;
    const int varow = cm * 64 + (l & 15);
    const int vac16 = l >> 4;
    const int pbrow = in_ * 32 + (l & 7) + ((l >> 4) << 3);
    const int pbc16 = (l >> 3) & 1;
    const int rl0   = wm * 32 + (l >> 2);

    float accD[4][4][4];
#pragma unroll
    for (int i = 0; i < 4; i++)
#pragma unroll
        for (int j = 0; j < 4; j++)
#pragma unroll
            for (int v = 0; v < 4; v++) accD[i][j][v] = 0.f;
    float rsum[4] = {0.f, 0.f, 0.f, 0.f};

    // ---- QK(s) + exp -> P[s&1], processed one im-half at a time ----
    auto qk_exp = [&](int s) {
        const uint32_t kb = sKa + (s & 1) * 8192u;
        const uint32_t pB = (uint32_t)FOFF_P + (s & 1) * 32768u + (uint32_t)wn * 8192u;

#pragma unroll
        for (int im = 0; im < 2; im++) {
            float S[4][4];
#pragma unroll
            for (int j = 0; j < 4; j++)
#pragma unroll
                for (int v = 0; v < 4; v++) S[j][v] = 0.f;

#pragma unroll
            for (int ks = 0; ks < 2; ks++) {
                uint32_t aq[4];
                {
                    int row = qarow + im * 16;
                    int c16 = ks * 2 + qac16;
                    ldsm4(aq, sQa + (uint32_t)row * 64u +
                                  (uint32_t)((c16 ^ ((row & 6) >> 1)) * 16));
                }
                uint32_t bk_[2][4];
#pragma unroll
                for (int ig = 0; ig < 2; ig++) {
                    int row = kbrow + ig * 16;
                    int c16 = ks * 2 + kbc16;
                    ldsm4(bk_[ig], kb + (uint32_t)row * 64u +
                                       (uint32_t)((c16 ^ ((row & 6) >> 1)) * 16));
                }
#pragma unroll
                for (int ig = 0; ig < 2; ig++) {
                    mma16816_f16(S[ig * 2 + 0], aq, &bk_[ig][0]);
                    mma16816_f16(S[ig * 2 + 1], aq, &bk_[ig][2]);
                }
            }

            const int row0 = rl0 + im * 16;
            const int row1 = row0 + 8;
            float s0 = 0.f, s1 = 0.f;
#pragma unroll
            for (int jn = 0; jn < 4; jn++) {
                float e0 = __expf(S[jn][0]);
                float e1 = __expf(S[jn][1]);
                float e2 = __expf(S[jn][2]);
                float e3 = __expf(S[jn][3]);
                uint32_t o0 = pB + sw64((uint32_t)row0 * 64u + (uint32_t)jn * 16u) + 4 * (l & 3);
                uint32_t o1 = pB + sw64((uint32_t)row1 * 64u + (uint32_t)jn * 16u) + 4 * (l & 3);
                *(__nv_bfloat162*)(smf + o0) = __floats2bfloat162_rn(e0, e1);
                *(__nv_bfloat162*)(smf + o1) = __floats2bfloat162_rn(e2, e3);
                s0 += e0 + e1;
                s1 += e2 + e3;
            }
            rsum[im * 2 + 0] += s0;
            rsum[im * 2 + 1] += s1;
        }
    };

    // ---- prologue: Q + K0 + K1 + V0 in one group ----
    {
        const __half* Qg = g_qT + ((size_t)b * LL + i0 + ldr) * C8 + ldc * 8;
        cp_async16(sQa + loff, Qg);
        const __half* Kg0 = g_kT + ((size_t)b * LL + ldr) * C8 + ldc * 8;
        cp_async16(sKa + loff, Kg0);
        const __half* Kg1 = g_kT + ((size_t)b * LL + 128 + ldr) * C8 + ldc * 8;
        cp_async16(sKa + 8192 + loff, Kg1);
        const __nv_bfloat16* Vg = g_vh + ((size_t)b * CC + vrow) * LL + vh * 64;
#pragma unroll
        for (int q = 0; q < 8; q++) {
            int sc = vh * 2 + (q >> 2);
            cp_async16(sVa + sc * 16384 + sw64((uint32_t)vrow * 64u + (uint32_t)(q & 3) * 16u),
                       Vg + q * 8);
        }
        CP_COMMIT();
        CP_WAIT(0);
        __syncthreads();
    }

    // QK(0) -> P[0]
    qk_exp(0);

    for (int jt = 0; jt < NJT; jt++) {
        CP_WAIT(0);
        __syncthreads();   // P(jt) sealed by all warps; stale buffers free

        // prefetch V(jt+1) -> vbuf[(jt+1)&1], K(jt+2) -> kbuf[jt&1]
        if (jt + 1 < NJT) {
            const __nv_bfloat16* Vg =
                g_vh + ((size_t)b * CC + vrow) * LL + (size_t)(jt + 1) * 128 + vh * 64;
            const uint32_t dst = sVa + ((jt + 1) & 1) * 65536;
#pragma unroll
            for (int q = 0; q < 8; q++) {
                int sc = vh * 2 + (q >> 2);
                cp_async16(dst + sc * 16384 +
                               sw64((uint32_t)vrow * 64u + (uint32_t)(q & 3) * 16u),
                           Vg + q * 8);
            }
            if (jt + 2 < NJT) {
                const __half* Kg2 =
                    g_kT + ((size_t)b * LL + (size_t)(jt + 2) * 128 + ldr) * C8 + ldc * 8;
                cp_async16(sKa + (jt & 1) * 8192 + loff, Kg2);
            }
            CP_COMMIT();
        }

        // QK(jt+1) + exp -> P[(jt+1)&1]  (K(jt+1) resident; no barrier needed)
        if (jt + 1 < NJT) qk_exp(jt + 1);

        // ---- PV(jt): accD += V[64c x 32j] * P[32i x 32j]^T, 4 sub-chunks ----
        const uint32_t vb = sVa + (jt & 1) * 65536;
        const uint32_t pT = sPa + (jt & 1) * 32768;
#pragma unroll
        for (int sc = 0; sc < 4; sc++) {
            const uint32_t va = vb + sc * 16384;
            const uint32_t pa = pT + sc * 8192;
#pragma unroll
            for (int ks = 0; ks < 2; ks++) {
                uint32_t bp[2][4];
#pragma unroll
                for (int ig = 0; ig < 2; ig++) {
                    int row = pbrow + ig * 16;
                    int c16 = ks * 2 + pbc16;
                    ldsm4(bp[ig], pa + (uint32_t)row * 64u +
                                      (uint32_t)((c16 ^ ((row & 6) >> 1)) * 16));
                }
#pragma unroll
                for (int half = 0; half < 2; half++) {
                    uint32_t af[2][4];
#pragma unroll
                    for (int i2 = 0; i2 < 2; i2++) {
                        int imm = half * 2 + i2;
                        int row = varow + imm * 16;
                        int c16 = ks * 2 + vac16;
                        ldsm4(af[i2], va + (uint32_t)row * 64u +
                                          (uint32_t)((c16 ^ ((row & 6) >> 1)) * 16));
                    }
#pragma unroll
                    for (int i2 = 0; i2 < 2; i2++) {
                        int imm = half * 2 + i2;
#pragma unroll
                        for (int ig = 0; ig < 2; ig++) {
                            mma16816_bf16(accD[imm][ig * 2 + 0], af[i2], &bp[ig][0]);
                            mma16816_bf16(accD[imm][ig * 2 + 1], af[i2], &bp[ig][2]);
                        }
                    }
                }
            }
        }
    }

    // ---- rowsum: quad shfl, stage per-wn, reduce ----
#pragma unroll
    for (int off = 1; off <= 2; off <<= 1)
#pragma unroll
        for (int r = 0; r < 4; r++)
            rsum[r] += __shfl_xor_sync(0xffffffffu, rsum[r], off);

    if ((l & 3) == 0) {
        srs[wn * 128 + rl0]      = rsum[0];
        srs[wn * 128 + rl0 + 8]  = rsum[1];
        srs[wn * 128 + rl0 + 16] = rsum[2];
        srs[wn * 128 + rl0 + 24] = rsum[3];
    }
    __syncthreads();
    if (t < 128)
        sInv[t] = 1.0f / (srs[t] + srs[128 + t] + srs[256 + t] + srs[384 + t]);
    __syncthreads();

    // ---- epilogue: normalize, gamma, residual ----
    const float g = *gamma;
#pragma unroll
    for (int imm = 0; imm < 4; imm++) {
        const int r0 = cm * 64 + imm * 16 + (l >> 2);
#pragma unroll
        for (int jn = 0; jn < 4; jn++) {
            const int ic = in_ * 32 + jn * 8 + 2 * (l & 3);
            float2 inv = *(float2*)&sInv[ic];

            size_t base0 = ((size_t)b * CC + r0) * LL + i0 + ic;
            float2 xv0 = *(const float2*)&x[base0];
            float2 o0;
            o0.x = g * accD[imm][jn][0] * inv.x + xv0.x;
            o0.y = g * accD[imm][jn][1] * inv.y + xv0.y;
            *(float2*)&out[base0] = o0;

            size_t base1 = base0 + (size_t)8 * LL;
            float2 xv1 = *(const float2*)&x[base1];
            float2 o1;
            o1.x = g * accD[imm][jn][2] * inv.x + xv1.x;
            o1.y = g * accD[imm][jn][3] * inv.y + xv1.y;
            *(float2*)&out[base1] = o1;
        }
    }
}

// ---------------- launch ----------------------------------------------------
extern "C" void kernel_launch(void* const* d_in, const int* in_sizes, int n_in,
                              void* d_out, int out_size) {
    const float* x     = (const float*)d_in[0];
    const float* Wq    = (const float*)d_in[1];
    const float* bq    = (const float*)d_in[2];
    const float* Wk    = (const float*)d_in[3];
    const float* bk    = (const float*)d_in[4];
    const float* Wv    = (const float*)d_in[5];
    const float* bv    = (const float*)d_in[6];
    const float* gamma = (const float*)d_in[7];
    float* out = (float*)d_out;

    cudaFuncSetAttribute(fused_attn_kernel,
                         cudaFuncAttributeMaxDynamicSharedMemorySize, FSM_TOTAL);

    pack_kernel<<<320, 256>>>(Wq, bq, Wk, bk, Wv, bv);
    xt_kernel<<<dim3(LL / 64, CC / 64, BB), 256>>>(x);
    qkvT_kernel<<<dim3(LL / 256, OTOT / 64, BB), 256>>>();
    fused_attn_kernel<<<dim3(LL / 128, BB), 512, FSM_TOTAL>>>(x, gamma, out);
}